// round 2
// baseline (speedup 1.0000x reference)
#include <cuda_runtime.h>
#include <math.h>

#define NQ        4
#define DIM       16
#define D_IN      256
#define D_OUT     64
#define THREADS   128
#define ROWS      128          // rows per block == threads per block

#define PI_F        3.14159265358979323846f
#define INV_SQRT2_F 0.70710678118654752440f

// Fixed 16x16 unitary (CNOT layers + Rot gates), row-major, 2 complex per float4.
__device__ float4 d_Ufix[DIM * DIM / 2];   // 128 x float4 = 2 KB

static __device__ __forceinline__ float2 cmul(float2 a, float2 b) {
    return make_float2(a.x * b.x - a.y * b.y, a.x * b.y + a.y * b.x);
}

// ---------------------------------------------------------------------------
// Setup kernel: build U_fix = (Rot layer ∘ CNOT layer)^L as a 16x16 matrix.
// Batch-independent, 16 active threads (one per column), negligible cost.
// State index convention: s = q0*8 + q1*4 + q2*2 + q3  (wire w <-> bit 3-w).
// ---------------------------------------------------------------------------
__global__ void setup_unitary(const float* __restrict__ weights, int n_layers)
{
    __shared__ float2 u[16][17];   // u[j][s] = column j of running unitary
    int j = threadIdx.x;
    if (j >= 16) return;

    for (int s = 0; s < 16; s++) u[j][s] = make_float2(s == j ? 1.f : 0.f, 0.f);

    const int cn[8][2] = {{0,1},{1,2},{2,3},{3,0},{0,2},{1,3},{2,0},{3,1}};

    for (int l = 0; l < n_layers; l++) {
        // CNOTs: U' = P·U  ->  u'[j][s] = u[j][C(s)]; C involution -> swap pairs
        for (int p = 0; p < 8; p++) {
            int bc = 3 - cn[p][0];
            int bt = 3 - cn[p][1];
            for (int s = 0; s < 16; s++) {
                if (((s >> bc) & 1) && !((s >> bt) & 1)) {
                    int s1 = s | (1 << bt);
                    float2 tmp = u[j][s]; u[j][s] = u[j][s1]; u[j][s1] = tmp;
                }
            }
        }
        // Rot(phi, theta, omega) = RZ(omega) @ RY(theta) @ RZ(phi) per wire
        for (int i = 0; i < 4; i++) {
            float phi = weights[(l * 4 + i) * 3 + 0];
            float th  = weights[(l * 4 + i) * 3 + 1];
            float om  = weights[(l * 4 + i) * 3 + 2];
            float st, ct;  sincosf(0.5f * th, &st, &ct);
            float ap = 0.5f * (phi + om), am = 0.5f * (phi - om);
            float sa, ca;  sincosf(ap, &sa, &ca);
            float sb, cb;  sincosf(am, &sb, &cb);
            float2 U00 = make_float2( ct * ca, -ct * sa);
            float2 U01 = make_float2(-st * cb, -st * sb);
            float2 U10 = make_float2( st * cb, -st * sb);
            float2 U11 = make_float2( ct * ca,  ct * sa);
            int b = 3 - i, m = 1 << b;
            for (int s = 0; s < 16; s++) {
                if (!((s >> b) & 1)) {
                    float2 a0 = u[j][s], a1 = u[j][s | m];
                    float2 n0 = cmul(U00, a0), t1 = cmul(U01, a1);
                    float2 n1 = cmul(U10, a0), t2 = cmul(U11, a1);
                    n0.x += t1.x; n0.y += t1.y;
                    n1.x += t2.x; n1.y += t2.y;
                    u[j][s] = n0; u[j][s | m] = n1;
                }
            }
        }
    }
    // Write row-major: d_U[s][t];  column j holds U[s][j]
    float2* Uc = (float2*)d_Ufix;
    for (int s = 0; s < 16; s++) Uc[s * 16 + j] = u[j][s];
}

// ---------------------------------------------------------------------------
// Main kernel. One block = 128 rows, 128 threads. Three phases:
//  1) f = tanh(x @ W1^T + b1) * pi        (8 threads/row, coalesced LDG.128)
//  2) product state + 16x16 matvec + <Z>  (1 thread/row, U_fix broadcast LDS)
//  3) out = q @ W2^T + b2                 (coalesced STG.128)
// ---------------------------------------------------------------------------
__global__ __launch_bounds__(THREADS)
void qproj_kernel(const float* __restrict__ x,  const float* __restrict__ W1,
                  const float* __restrict__ b1, const float* __restrict__ W2,
                  const float* __restrict__ b2, float* __restrict__ out, int B)
{
    __shared__ float4 us[128];     // U_fix, 2 KB
    __shared__ float4 w1s[256];    // W1 (4x256) as float4: w1s[i*64 + c4], 4 KB
    __shared__ float4 fs[ROWS];    // f per row
    __shared__ float4 qs[ROWS];    // <Z_i> per row
    __shared__ float  b1s[4];

    const int t = threadIdx.x;
    us[t]        = d_Ufix[t];
    w1s[t]       = ((const float4*)W1)[t];
    w1s[t + 128] = ((const float4*)W1)[t + 128];
    if (t < 4) b1s[t] = b1[t];
    __syncthreads();

    const int row0 = blockIdx.x * ROWS;
    const int j = t & 7;        // lane within 8-thread row group
    const int g = t >> 3;       // group id 0..15

    // ---- Phase 1: x @ W1^T -------------------------------------------------
    float4 acc[8];
    bool inb[8];
    #pragma unroll
    for (int r = 0; r < 8; r++) {
        acc[r] = make_float4(0.f, 0.f, 0.f, 0.f);
        inb[r] = (row0 + r * 16 + g) < B;
    }

    for (int m = 0; m < 8; m++) {
        float4 wv0 = w1s[0 * 64 + m * 8 + j];
        float4 wv1 = w1s[1 * 64 + m * 8 + j];
        float4 wv2 = w1s[2 * 64 + m * 8 + j];
        float4 wv3 = w1s[3 * 64 + m * 8 + j];
        #pragma unroll
        for (int r = 0; r < 8; r++) {
            float4 xv = make_float4(0.f, 0.f, 0.f, 0.f);
            if (inb[r]) {
                int row = row0 + r * 16 + g;
                xv = __ldg((const float4*)(x + (size_t)row * D_IN + m * 32 + j * 4));
            }
            acc[r].x = fmaf(xv.x, wv0.x, fmaf(xv.y, wv0.y, fmaf(xv.z, wv0.z, fmaf(xv.w, wv0.w, acc[r].x))));
            acc[r].y = fmaf(xv.x, wv1.x, fmaf(xv.y, wv1.y, fmaf(xv.z, wv1.z, fmaf(xv.w, wv1.w, acc[r].y))));
            acc[r].z = fmaf(xv.x, wv2.x, fmaf(xv.y, wv2.y, fmaf(xv.z, wv2.z, fmaf(xv.w, wv2.w, acc[r].z))));
            acc[r].w = fmaf(xv.x, wv3.x, fmaf(xv.y, wv3.y, fmaf(xv.z, wv3.z, fmaf(xv.w, wv3.w, acc[r].w))));
        }
    }
    #pragma unroll
    for (int r = 0; r < 8; r++) {
        #pragma unroll
        for (int off = 1; off < 8; off <<= 1) {
            acc[r].x += __shfl_xor_sync(0xffffffffu, acc[r].x, off);
            acc[r].y += __shfl_xor_sync(0xffffffffu, acc[r].y, off);
            acc[r].z += __shfl_xor_sync(0xffffffffu, acc[r].z, off);
            acc[r].w += __shfl_xor_sync(0xffffffffu, acc[r].w, off);
        }
        if (j == 0) {
            float4 f;
            f.x = tanhf(acc[r].x + b1s[0]) * PI_F;
            f.y = tanhf(acc[r].y + b1s[1]) * PI_F;
            f.z = tanhf(acc[r].z + b1s[2]) * PI_F;
            f.w = tanhf(acc[r].w + b1s[3]) * PI_F;
            fs[r * 16 + g] = f;
        }
    }
    __syncthreads();

    // ---- Phase 2: encode -> product state -> U_fix matvec -> <Z_i> ---------
    {
        float4 f4 = fs[t];
        float fv[4] = {f4.x, f4.y, f4.z, f4.w};
        float2 va[4], vb[4];   // per-wire 2-vector components
        #pragma unroll
        for (int i = 0; i < 4; i++) {
            float fi = fv[i];
            // theta = atan(fi): cos(theta) = rsqrt(1+fi^2); half-angle identities
            float c   = rsqrtf(fmaf(fi, fi, 1.f));
            float t2  = 0.5f * (1.f + c);
            float rh  = rsqrtf(t2);
            float ch  = t2 * rh;                 // cos(theta/2)
            float sh  = 0.5f * fi * c * rh;      // sin(theta/2)
            float a0  = (ch - sh) * INV_SQRT2_F; // RY * H|0>, real
            float a1  = (ch + sh) * INV_SQRT2_F;
            // phi = atan(fi^2)
            float gg  = fi * fi;
            float cp  = rsqrtf(fmaf(gg, gg, 1.f));
            float tp  = 0.5f * (1.f + cp);
            float rp  = rsqrtf(tp);
            float chp = tp * rp;                 // cos(phi/2)
            float shp = 0.5f * gg * cp * rp;     // sin(phi/2)
            va[i] = make_float2(a0 * chp, -a0 * shp);   // comp0 * e^{-i phi/2}
            vb[i] = make_float2(a1 * chp,  a1 * shp);   // comp1 * e^{+i phi/2}
        }
        // product state psi[s], s = q0*8 + q1*4 + q2*2 + q3
        float2 p01[4], p012[8], psi[16];
        #pragma unroll
        for (int q0 = 0; q0 < 2; q0++)
            #pragma unroll
            for (int q1 = 0; q1 < 2; q1++)
                p01[q0 * 2 + q1] = cmul(q0 ? vb[0] : va[0], q1 ? vb[1] : va[1]);
        #pragma unroll
        for (int a = 0; a < 4; a++)
            #pragma unroll
            for (int q2 = 0; q2 < 2; q2++)
                p012[a * 2 + q2] = cmul(p01[a], q2 ? vb[2] : va[2]);
        #pragma unroll
        for (int a = 0; a < 8; a++)
            #pragma unroll
            for (int q3 = 0; q3 < 2; q3++)
                psi[a * 2 + q3] = cmul(p012[a], q3 ? vb[3] : va[3]);

        // out_s = sum_t U[s][t] psi[t]; accumulate signed |out_s|^2
        float z0 = 0.f, z1 = 0.f, z2 = 0.f, z3 = 0.f;
        #pragma unroll
        for (int s = 0; s < 16; s++) {
            float ar = 0.f, ai = 0.f;
            #pragma unroll
            for (int h = 0; h < 8; h++) {
                float4 uu = us[s * 8 + h];        // complex t=2h, 2h+1
                float2 pa = psi[2 * h], pb = psi[2 * h + 1];
                ar = fmaf(uu.x, pa.x, ar); ar = fmaf(-uu.y, pa.y, ar);
                ai = fmaf(uu.x, pa.y, ai); ai = fmaf( uu.y, pa.x, ai);
                ar = fmaf(uu.z, pb.x, ar); ar = fmaf(-uu.w, pb.y, ar);
                ai = fmaf(uu.z, pb.y, ai); ai = fmaf( uu.w, pb.x, ai);
            }
            float p = fmaf(ar, ar, ai * ai);
            z0 += (s & 8) ? -p : p;
            z1 += (s & 4) ? -p : p;
            z2 += (s & 2) ? -p : p;
            z3 += (s & 1) ? -p : p;
        }
        qs[t] = make_float4(z0, z1, z2, z3);
    }
    __syncthreads();

    // ---- Phase 3: out = q @ W2^T + b2, coalesced float4 stores -------------
    {
        const int o4 = (t & 15) * 4;           // 4 consecutive output cols
        float4 w2r[4];
        #pragma unroll
        for (int e = 0; e < 4; e++)
            w2r[e] = __ldg((const float4*)(W2 + (size_t)(o4 + e) * 4));
        float4 b2v = __ldg((const float4*)(b2 + o4));
        const int rb = t >> 4;                 // 0..7
        for (int k = 0; k < 16; k++) {
            int r = rb + k * 8;
            int row = row0 + r;
            if (row >= B) break;
            float4 q4 = qs[r];
            float4 o;
            o.x = fmaf(q4.x, w2r[0].x, fmaf(q4.y, w2r[0].y, fmaf(q4.z, w2r[0].z, fmaf(q4.w, w2r[0].w, b2v.x))));
            o.y = fmaf(q4.x, w2r[1].x, fmaf(q4.y, w2r[1].y, fmaf(q4.z, w2r[1].z, fmaf(q4.w, w2r[1].w, b2v.y))));
            o.z = fmaf(q4.x, w2r[2].x, fmaf(q4.y, w2r[2].y, fmaf(q4.z, w2r[2].z, fmaf(q4.w, w2r[2].w, b2v.z))));
            o.w = fmaf(q4.x, w2r[3].x, fmaf(q4.y, w2r[3].y, fmaf(q4.z, w2r[3].z, fmaf(q4.w, w2r[3].w, b2v.w))));
            *(float4*)(out + (size_t)row * D_OUT + o4) = o;
        }
    }
}

// ---------------------------------------------------------------------------
extern "C" void kernel_launch(void* const* d_in, const int* in_sizes, int n_in,
                              void* d_out, int out_size)
{
    (void)n_in; (void)out_size;
    const float* x       = (const float*)d_in[0];
    const float* W1      = (const float*)d_in[1];
    const float* b1      = (const float*)d_in[2];
    const float* weights = (const float*)d_in[3];
    const float* W2      = (const float*)d_in[4];
    const float* b2      = (const float*)d_in[5];
    float* out = (float*)d_out;

    int B        = in_sizes[0] / D_IN;
    int n_layers = in_sizes[3] / 12;

    setup_unitary<<<1, 32>>>(weights, n_layers);
    int nb = (B + ROWS - 1) / ROWS;
    qproj_kernel<<<nb, THREADS>>>(x, W1, b1, W2, b2, out, B);
}

// round 3
// speedup vs baseline: 1.1648x; 1.1648x over previous
#include <cuda_runtime.h>
#include <math.h>

#define D_IN     256
#define D_OUT    64
#define THREADS  128
#define ROWS     64
#define PI_F     3.14159265358979323846f

typedef unsigned long long u64;

// Expanded fixed unitary: entry [s][t] stored as float4(re, re, im, im).
__device__ float4 d_UfixE[256];   // 4 KB

// ---- packed f32x2 helpers (sm_100+) ---------------------------------------
static __device__ __forceinline__ u64 ffma2(u64 a, u64 b, u64 c) {
    u64 d; asm("fma.rn.f32x2 %0, %1, %2, %3;" : "=l"(d) : "l"(a), "l"(b), "l"(c)); return d;
}
static __device__ __forceinline__ u64 fadd2(u64 a, u64 b) {
    u64 d; asm("add.rn.f32x2 %0, %1, %2;" : "=l"(d) : "l"(a), "l"(b)); return d;
}
static __device__ __forceinline__ u64 pack2(float lo, float hi) {
    u64 d; asm("mov.b64 %0, {%1, %2};" : "=l"(d) : "f"(lo), "f"(hi)); return d;
}
static __device__ __forceinline__ void unpack2(u64 v, float& lo, float& hi) {
    asm("mov.b64 {%0, %1}, %2;" : "=f"(lo), "=f"(hi) : "l"(v));
}
static __device__ __forceinline__ float2 cmulf(float2 a, float2 b) {
    return make_float2(a.x * b.x - a.y * b.y, a.x * b.y + a.y * b.x);
}

// ---------------------------------------------------------------------------
// Setup kernel: build U_fix = (Rot layer ∘ CNOT layer)^L, write expanded form.
// ---------------------------------------------------------------------------
__global__ void setup_unitary(const float* __restrict__ weights, int n_layers)
{
    __shared__ float2 u[16][17];
    int j = threadIdx.x;
    if (j >= 16) return;

    for (int s = 0; s < 16; s++) u[j][s] = make_float2(s == j ? 1.f : 0.f, 0.f);

    const int cn[8][2] = {{0,1},{1,2},{2,3},{3,0},{0,2},{1,3},{2,0},{3,1}};

    for (int l = 0; l < n_layers; l++) {
        for (int p = 0; p < 8; p++) {
            int bc = 3 - cn[p][0];
            int bt = 3 - cn[p][1];
            for (int s = 0; s < 16; s++) {
                if (((s >> bc) & 1) && !((s >> bt) & 1)) {
                    int s1 = s | (1 << bt);
                    float2 tmp = u[j][s]; u[j][s] = u[j][s1]; u[j][s1] = tmp;
                }
            }
        }
        for (int i = 0; i < 4; i++) {
            float phi = weights[(l * 4 + i) * 3 + 0];
            float th  = weights[(l * 4 + i) * 3 + 1];
            float om  = weights[(l * 4 + i) * 3 + 2];
            float st, ct;  __sincosf(0.5f * th, &st, &ct);
            float sa, ca;  __sincosf(0.5f * (phi + om), &sa, &ca);
            float sb, cb;  __sincosf(0.5f * (phi - om), &sb, &cb);
            float2 U00 = make_float2( ct * ca, -ct * sa);
            float2 U01 = make_float2(-st * cb, -st * sb);
            float2 U10 = make_float2( st * cb, -st * sb);
            float2 U11 = make_float2( ct * ca,  ct * sa);
            int b = 3 - i, m = 1 << b;
            for (int s = 0; s < 16; s++) {
                if (!((s >> b) & 1)) {
                    float2 a0 = u[j][s], a1 = u[j][s | m];
                    float2 n0 = cmulf(U00, a0), t1 = cmulf(U01, a1);
                    float2 n1 = cmulf(U10, a0), t2 = cmulf(U11, a1);
                    n0.x += t1.x; n0.y += t1.y;
                    n1.x += t2.x; n1.y += t2.y;
                    u[j][s] = n0; u[j][s | m] = n1;
                }
            }
        }
    }
    // column j holds U[s][j]; write expanded (re,re,im,im)
    for (int s = 0; s < 16; s++) {
        float2 c = u[j][s];
        d_UfixE[s * 16 + j] = make_float4(c.x, c.x, c.y, c.y);
    }
}

// ---------------------------------------------------------------------------
// Main kernel: 64 rows / 128 threads per block.
// ---------------------------------------------------------------------------
__global__ __launch_bounds__(THREADS, 8)
void qproj_kernel(const float* __restrict__ x,  const float* __restrict__ W1,
                  const float* __restrict__ b1, const float* __restrict__ W2,
                  const float* __restrict__ b2, float* __restrict__ out, int B)
{
    __shared__ double2 usx[256];     // expanded U: [s*16+t] = ((re,re),(im,im)), 4 KB
    __shared__ double2 w1s[256];     // W1 row-major as 16B chunks, 4 KB
    __shared__ float4  fs[ROWS];     // f per row
    __shared__ float4  qs2[ROWS][2]; // partial <Z_i> per row, per half
    __shared__ float   b1s[4];

    const int t = threadIdx.x;
    usx[t]        = ((const double2*)d_UfixE)[t];
    usx[t + 128]  = ((const double2*)d_UfixE)[t + 128];
    w1s[t]        = ((const double2*)W1)[t];
    w1s[t + 128]  = ((const double2*)W1)[t + 128];
    if (t < 4) b1s[t] = b1[t];
    __syncthreads();

    const int row0 = blockIdx.x * ROWS;
    const int j = t & 7;       // lane within 8-thread row group
    const int g = t >> 3;      // group id 0..15

    // ---- Phase 1: f = tanh(x @ W1^T + b1) * pi  (packed even/odd dot) ------
    {
        u64 acc[4][4];
        #pragma unroll
        for (int r = 0; r < 4; r++)
            #pragma unroll
            for (int i = 0; i < 4; i++) acc[r][i] = 0ull;

        bool ok[4];
        #pragma unroll
        for (int r = 0; r < 4; r++) ok[r] = (row0 + r * 16 + g) < B;

        const float* xb = x + (size_t)(row0 + g) * D_IN + j * 4;

        #pragma unroll
        for (int m = 0; m < 8; m++) {
            double2 wv0 = w1s[0 * 64 + m * 8 + j];
            double2 wv1 = w1s[1 * 64 + m * 8 + j];
            double2 wv2 = w1s[2 * 64 + m * 8 + j];
            double2 wv3 = w1s[3 * 64 + m * 8 + j];
            u64 w0a = __double_as_longlong(wv0.x), w0b = __double_as_longlong(wv0.y);
            u64 w1a = __double_as_longlong(wv1.x), w1b = __double_as_longlong(wv1.y);
            u64 w2a = __double_as_longlong(wv2.x), w2b = __double_as_longlong(wv2.y);
            u64 w3a = __double_as_longlong(wv3.x), w3b = __double_as_longlong(wv3.y);
            #pragma unroll
            for (int r = 0; r < 4; r++) {
                double2 xv = make_double2(0.0, 0.0);
                if (ok[r]) xv = __ldg((const double2*)(xb + r * 16 * D_IN + m * 32));
                u64 xa = __double_as_longlong(xv.x);
                u64 xbp = __double_as_longlong(xv.y);
                acc[r][0] = ffma2(xa, w0a, acc[r][0]); acc[r][0] = ffma2(xbp, w0b, acc[r][0]);
                acc[r][1] = ffma2(xa, w1a, acc[r][1]); acc[r][1] = ffma2(xbp, w1b, acc[r][1]);
                acc[r][2] = ffma2(xa, w2a, acc[r][2]); acc[r][2] = ffma2(xbp, w2b, acc[r][2]);
                acc[r][3] = ffma2(xa, w3a, acc[r][3]); acc[r][3] = ffma2(xbp, w3b, acc[r][3]);
            }
        }
        #pragma unroll
        for (int r = 0; r < 4; r++) {
            #pragma unroll
            for (int i = 0; i < 4; i++) {
                u64 v = acc[r][i];
                v = fadd2(v, __shfl_xor_sync(0xffffffffu, v, 1));
                v = fadd2(v, __shfl_xor_sync(0xffffffffu, v, 2));
                v = fadd2(v, __shfl_xor_sync(0xffffffffu, v, 4));
                acc[r][i] = v;
            }
            if (j == 0) {
                float fv[4];
                #pragma unroll
                for (int i = 0; i < 4; i++) {
                    float e, o; unpack2(acc[r][i], e, o);
                    fv[i] = tanhf(e + o + b1s[i]) * PI_F;
                }
                fs[r * 16 + g] = make_float4(fv[0], fv[1], fv[2], fv[3]);
            }
        }
    }
    __syncthreads();

    // ---- Phase 2: encode -> product state -> packed matvec -> <Z_i> --------
    {
        const int row  = t & 63;
        const int half = t >> 6;
        float4 f4 = fs[row];
        float fv[4] = {f4.x, f4.y, f4.z, f4.w};

        // per-wire state (global phase per qubit dropped): v = (ra real, cb complex)
        float ra[4]; float2 cb[4];
        #pragma unroll
        for (int i = 0; i < 4; i++) {
            float fi = fv[i];
            float c  = rsqrtf(fmaf(fi, fi, 1.f));   // cos(atan f)
            float fc = fi * c;                       // sin(atan f)
            float t0 = 0.5f - 0.5f * fc;             // (1 - sin)/2  >= ~0.023
            float t1 = 0.5f + 0.5f * fc;
            ra[i]    = t0 * rsqrtf(t0);              // sqrt(t0) = (ch-sh)/sqrt2
            float a1 = t1 * rsqrtf(t1);              // (ch+sh)/sqrt2
            float gg = fi * fi;
            float cp = rsqrtf(fmaf(gg, gg, 1.f));    // cos(atan g)
            float mm = a1 * cp;
            cb[i] = make_float2(mm, mm * gg);        // a1 * e^{i phi}
        }

        // product state, structure-aware (entry 0 of each partial is real)
        float  p0  = ra[0] * ra[1];
        float2 p1  = make_float2(ra[0] * cb[1].x, ra[0] * cb[1].y);
        float2 p2  = make_float2(cb[0].x * ra[1], cb[0].y * ra[1]);
        float2 p3  = cmulf(cb[0], cb[1]);

        float  q0  = p0 * ra[2];
        float2 q1  = make_float2(p0 * cb[2].x, p0 * cb[2].y);
        float2 q2  = make_float2(p1.x * ra[2], p1.y * ra[2]);
        float2 q3  = cmulf(p1, cb[2]);
        float2 q4  = make_float2(p2.x * ra[2], p2.y * ra[2]);
        float2 q5  = cmulf(p2, cb[2]);
        float2 q6  = make_float2(p3.x * ra[2], p3.y * ra[2]);
        float2 q7  = cmulf(p3, cb[2]);

        u64 pp[16];
        {
            float r3 = ra[3]; float2 c3 = cb[3];
            pp[ 0] = pack2(q0 * r3, 0.f);
            pp[ 1] = pack2(q0 * c3.x, q0 * c3.y);
            float2 e;
            e = make_float2(q1.x * r3, q1.y * r3);  pp[ 2] = pack2(e.x, e.y);
            e = cmulf(q1, c3);                      pp[ 3] = pack2(e.x, e.y);
            e = make_float2(q2.x * r3, q2.y * r3);  pp[ 4] = pack2(e.x, e.y);
            e = cmulf(q2, c3);                      pp[ 5] = pack2(e.x, e.y);
            e = make_float2(q3.x * r3, q3.y * r3);  pp[ 6] = pack2(e.x, e.y);
            e = cmulf(q3, c3);                      pp[ 7] = pack2(e.x, e.y);
            e = make_float2(q4.x * r3, q4.y * r3);  pp[ 8] = pack2(e.x, e.y);
            e = cmulf(q4, c3);                      pp[ 9] = pack2(e.x, e.y);
            e = make_float2(q5.x * r3, q5.y * r3);  pp[10] = pack2(e.x, e.y);
            e = cmulf(q5, c3);                      pp[11] = pack2(e.x, e.y);
            e = make_float2(q6.x * r3, q6.y * r3);  pp[12] = pack2(e.x, e.y);
            e = cmulf(q6, c3);                      pp[13] = pack2(e.x, e.y);
            e = make_float2(q7.x * r3, q7.y * r3);  pp[14] = pack2(e.x, e.y);
            e = cmulf(q7, c3);                      pp[15] = pack2(e.x, e.y);
        }

        // half-matvec: s in [half*8, half*8+8), packed complex MAC
        const int sbase = half * 8;
        float zs = 0.f, z1v = 0.f, z2v = 0.f, z3v = 0.f;
        #pragma unroll
        for (int k = 0; k < 8; k++) {
            const double2* urow = &usx[(sbase + k) * 16];
            u64 accA = 0ull, accB = 0ull;
            #pragma unroll
            for (int h = 0; h < 16; h++) {
                double2 uu = urow[h];
                u64 rr = __double_as_longlong(uu.x);   // (re, re)
                u64 ii = __double_as_longlong(uu.y);   // (im, im)
                accA = ffma2(rr, pp[h], accA);
                accB = ffma2(ii, pp[h], accB);
            }
            float Ax, Ay, Bx, By;
            unpack2(accA, Ax, Ay);
            unpack2(accB, Bx, By);
            float ar = Ax - By;
            float ai = Ay + Bx;
            float p  = fmaf(ar, ar, ai * ai);
            zs += p;
            z1v += (k & 4) ? -p : p;
            z2v += (k & 2) ? -p : p;
            z3v += (k & 1) ? -p : p;
        }
        float z0v = half ? -zs : zs;
        qs2[row][half] = make_float4(z0v, z1v, z2v, z3v);
    }
    __syncthreads();

    // ---- Phase 3: out = q @ W2^T + b2, coalesced float4 stores -------------
    {
        const int o4 = (t & 15) * 4;
        const int rb = t >> 4;                    // 0..7
        float4 w2r0 = __ldg((const float4*)(W2 + (size_t)(o4 + 0) * 4));
        float4 w2r1 = __ldg((const float4*)(W2 + (size_t)(o4 + 1) * 4));
        float4 w2r2 = __ldg((const float4*)(W2 + (size_t)(o4 + 2) * 4));
        float4 w2r3 = __ldg((const float4*)(W2 + (size_t)(o4 + 3) * 4));
        float4 b2v  = __ldg((const float4*)(b2 + o4));
        #pragma unroll
        for (int k = 0; k < 8; k++) {
            int r   = rb + k * 8;
            int row = row0 + r;
            if (row < B) {
                float4 qa = qs2[r][0], qb = qs2[r][1];
                float4 q4 = make_float4(qa.x + qb.x, qa.y + qb.y,
                                        qa.z + qb.z, qa.w + qb.w);
                float4 o;
                o.x = fmaf(q4.x, w2r0.x, fmaf(q4.y, w2r0.y, fmaf(q4.z, w2r0.z, fmaf(q4.w, w2r0.w, b2v.x))));
                o.y = fmaf(q4.x, w2r1.x, fmaf(q4.y, w2r1.y, fmaf(q4.z, w2r1.z, fmaf(q4.w, w2r1.w, b2v.y))));
                o.z = fmaf(q4.x, w2r2.x, fmaf(q4.y, w2r2.y, fmaf(q4.z, w2r2.z, fmaf(q4.w, w2r2.w, b2v.z))));
                o.w = fmaf(q4.x, w2r3.x, fmaf(q4.y, w2r3.y, fmaf(q4.z, w2r3.z, fmaf(q4.w, w2r3.w, b2v.w))));
                *(float4*)(out + (size_t)row * D_OUT + o4) = o;
            }
        }
    }
}

// ---------------------------------------------------------------------------
extern "C" void kernel_launch(void* const* d_in, const int* in_sizes, int n_in,
                              void* d_out, int out_size)
{
    (void)n_in; (void)out_size;
    const float* x       = (const float*)d_in[0];
    const float* W1      = (const float*)d_in[1];
    const float* b1      = (const float*)d_in[2];
    const float* weights = (const float*)d_in[3];
    const float* W2      = (const float*)d_in[4];
    const float* b2      = (const float*)d_in[5];
    float* out = (float*)d_out;

    int B        = in_sizes[0] / D_IN;
    int n_layers = in_sizes[3] / 12;

    setup_unitary<<<1, 32>>>(weights, n_layers);
    int nb = (B + ROWS - 1) / ROWS;
    qproj_kernel<<<nb, THREADS>>>(x, W1, b1, W2, b2, out, B);
}